// round 2
// baseline (speedup 1.0000x reference)
#include <cuda_runtime.h>
#include <cstdint>
#include <cstddef>

// Problem constants
#define B_    2
#define S_    2048
#define D_    1024
#define H_    16
#define DK_   64
#define MTOT  4096        // B_*S_
#define HB_   32          // H_*B_

// ---------------------------------------------------------------------------
// Scratch (static device allocations; no dynamic alloc allowed)
// ---------------------------------------------------------------------------
static __device__ float g_qx[B_ * H_ * S_ * DK_];   // [b][h][s][dk]
static __device__ float g_kx[B_ * H_ * S_ * DK_];
static __device__ float g_vx[B_ * H_ * S_ * DK_];
static __device__ float g_ctx[(size_t)MTOT * D_];   // [b*S+s][h*64+dk]
static __device__ float g_dense[(size_t)MTOT * D_];
static __device__ float g_rinv[HB_ * S_];           // 1/rowsum per attn row

// ---------------------------------------------------------------------------
// Helpers
// ---------------------------------------------------------------------------
__device__ __forceinline__ float tf32_hi(float x) {
    uint32_t r;
    asm("cvt.rna.tf32.f32 %0, %1;" : "=r"(r) : "f"(x));
    return __uint_as_float(r);
}

__device__ __forceinline__ void mma_tf32(float c[4],
                                         uint32_t a0, uint32_t a1, uint32_t a2, uint32_t a3,
                                         uint32_t b0, uint32_t b1) {
    asm volatile(
        "mma.sync.aligned.m16n8k8.row.col.f32.tf32.tf32.f32 "
        "{%0,%1,%2,%3}, {%4,%5,%6,%7}, {%8,%9}, {%0,%1,%2,%3};\n"
        : "+f"(c[0]), "+f"(c[1]), "+f"(c[2]), "+f"(c[3])
        : "r"(a0), "r"(a1), "r"(a2), "r"(a3), "r"(b0), "r"(b1));
}

// ---------------------------------------------------------------------------
// Generic 3xTF32 GEMM:  C[4096 x 1024] = A[4096 x 1024] @ W[1024 x 1024]^T + bias
// mode 0/1/2 : scatter into g_qx/g_kx/g_vx as [b][h][s][dk]
// mode 3     : A = g_ctx (arg ignored), out = relu(C) into g_dense row-major
// BM=128 BN=128 BK=16, 256 threads, warps 2(m) x 4(n), warp tile 64x32
// ---------------------------------------------------------------------------
__global__ __launch_bounds__(256) void proj_gemm(const float* __restrict__ A,
                                                 const float* __restrict__ W,
                                                 const float* __restrict__ bias,
                                                 int mode) {
    __shared__ float As_h[128 * 20];
    __shared__ float As_l[128 * 20];
    __shared__ float Bs_h[128 * 20];
    __shared__ float Bs_l[128 * 20];

    const float* Ap = (mode == 3) ? g_ctx : A;

    const int tid  = threadIdx.x;
    const int lane = tid & 31;
    const int warp = tid >> 5;
    const int wm   = warp & 1;    // 0..1
    const int wn   = warp >> 1;   // 0..3
    const int m0   = blockIdx.x * 128;
    const int n0   = blockIdx.y * 128;

    float c[4][4][4];
#pragma unroll
    for (int i = 0; i < 4; i++)
#pragma unroll
        for (int j = 0; j < 4; j++)
#pragma unroll
            for (int k = 0; k < 4; k++) c[i][j][k] = 0.f;

    for (int k0 = 0; k0 < 1024; k0 += 16) {
        // cooperative load + tf32 hi/lo split
#pragma unroll
        for (int i = 0; i < 2; i++) {
            int lin = tid + i * 256;          // 0..511 float4 slots
            int r   = lin >> 2;               // 0..127
            int c4  = (lin & 3) * 4;          // 0,4,8,12
            float4 av = *(const float4*)(Ap + (size_t)(m0 + r) * 1024 + k0 + c4);
            float4 ah, al;
            ah.x = tf32_hi(av.x); al.x = av.x - ah.x;
            ah.y = tf32_hi(av.y); al.y = av.y - ah.y;
            ah.z = tf32_hi(av.z); al.z = av.z - ah.z;
            ah.w = tf32_hi(av.w); al.w = av.w - ah.w;
            *(float4*)(As_h + r * 20 + c4) = ah;
            *(float4*)(As_l + r * 20 + c4) = al;

            float4 bvv = *(const float4*)(W + (size_t)(n0 + r) * 1024 + k0 + c4);
            float4 bh, bl;
            bh.x = tf32_hi(bvv.x); bl.x = bvv.x - bh.x;
            bh.y = tf32_hi(bvv.y); bl.y = bvv.y - bh.y;
            bh.z = tf32_hi(bvv.z); bl.z = bvv.z - bh.z;
            bh.w = tf32_hi(bvv.w); bl.w = bvv.w - bh.w;
            *(float4*)(Bs_h + r * 20 + c4) = bh;
            *(float4*)(Bs_l + r * 20 + c4) = bl;
        }
        __syncthreads();

#pragma unroll
        for (int kg = 0; kg < 16; kg += 8) {
            uint32_t bh[4][2], bl[4][2];
#pragma unroll
            for (int nt = 0; nt < 4; nt++) {
                int boff = (wn * 32 + nt * 8 + (lane >> 2)) * 20 + kg + (lane & 3);
                bh[nt][0] = __float_as_uint(Bs_h[boff]);
                bh[nt][1] = __float_as_uint(Bs_h[boff + 4]);
                bl[nt][0] = __float_as_uint(Bs_l[boff]);
                bl[nt][1] = __float_as_uint(Bs_l[boff + 4]);
            }
#pragma unroll
            for (int mt = 0; mt < 4; mt++) {
                int aoff = (wm * 64 + mt * 16 + (lane >> 2)) * 20 + kg + (lane & 3);
                uint32_t ah0 = __float_as_uint(As_h[aoff]);
                uint32_t ah1 = __float_as_uint(As_h[aoff + 8 * 20]);
                uint32_t ah2 = __float_as_uint(As_h[aoff + 4]);
                uint32_t ah3 = __float_as_uint(As_h[aoff + 8 * 20 + 4]);
                uint32_t al0 = __float_as_uint(As_l[aoff]);
                uint32_t al1 = __float_as_uint(As_l[aoff + 8 * 20]);
                uint32_t al2 = __float_as_uint(As_l[aoff + 4]);
                uint32_t al3 = __float_as_uint(As_l[aoff + 8 * 20 + 4]);
#pragma unroll
                for (int nt = 0; nt < 4; nt++) {
                    mma_tf32(c[mt][nt], ah0, ah1, ah2, ah3, bh[nt][0], bh[nt][1]);
                    mma_tf32(c[mt][nt], ah0, ah1, ah2, ah3, bl[nt][0], bl[nt][1]);
                    mma_tf32(c[mt][nt], al0, al1, al2, al3, bh[nt][0], bh[nt][1]);
                }
            }
        }
        __syncthreads();
    }

    // epilogue
#pragma unroll
    for (int mt = 0; mt < 4; mt++) {
#pragma unroll
        for (int nt = 0; nt < 4; nt++) {
#pragma unroll
            for (int j = 0; j < 4; j++) {
                int row = m0 + wm * 64 + mt * 16 + (lane >> 2) + ((j >> 1) << 3);
                int col = n0 + wn * 32 + nt * 8 + 2 * (lane & 3) + (j & 1);
                float v = c[mt][nt][j] + bias[col];
                if (mode == 3) {
                    g_dense[(size_t)row * 1024 + col] = v > 0.f ? v : 0.f;
                } else {
                    int b  = row >> 11;
                    int s  = row & 2047;
                    int h  = col >> 6;
                    int dk = col & 63;
                    float* dst = (mode == 0) ? g_qx : (mode == 1) ? g_kx : g_vx;
                    dst[(((size_t)(b * H_ + h)) * S_ + s) * DK_ + dk] = v;
                }
            }
        }
    }
}

// ---------------------------------------------------------------------------
// Fused attention kernel.
// grid = (S/64, H*B), block = 256 threads (8 warps as 4(m) x 2(n), warp 16x32)
// Per block: Q tile (64 rows) resident; loop over 32 k-tiles of 64:
//   S = Q K^T (tf32 1x) -> P = exp(S) -> write unnorm P to attn gmem,
//   accumulate rowsum (smem atomics) and O += P @ V (3xTF32).
// Epilogue: O * (1/rowsum) -> g_ctx; store 1/rowsum to g_rinv.
// ---------------------------------------------------------------------------
#define ATTN_SMEM_FLOATS (6 * 64 * 68 + 64)

__global__ __launch_bounds__(256) void attn_kernel(float* __restrict__ attn_out) {
    extern __shared__ float smf[];
    float* Qh  = smf;                 // 64x68 (tf32 hi, pre-scaled by 1/TEMP)
    float* Kh  = Qh + 64 * 68;        // 64x68 (tf32 hi)
    float* Vth = Kh + 64 * 68;        // transposed V hi: [d][kk]
    float* Vtl = Vth + 64 * 68;       // transposed V lo
    float* Ph  = Vtl + 64 * 68;       // P hi
    float* Pl  = Ph + 64 * 68;        // P lo
    float* rs  = Pl + 64 * 68;        // rowsum[64]

    const int tid  = threadIdx.x;
    const int lane = tid & 31;
    const int warp = tid >> 5;
    const int wm   = warp & 3;        // 0..3 -> q rows wm*16
    const int wn   = warp >> 2;       // 0..1 -> cols wn*32
    const int hb   = blockIdx.y;
    const int h    = hb >> 1;         // hb = h*B + b, B=2
    const int b    = hb & 1;
    const int q0   = blockIdx.x * 64;

    const float* qbase = g_qx + ((size_t)(b * H_ + h)) * S_ * DK_;
    const float* kbase = g_kx + ((size_t)(b * H_ + h)) * S_ * DK_;
    const float* vbase = g_vx + ((size_t)(b * H_ + h)) * S_ * DK_;
    const float invT = 0.03125f;      // 1/sqrt(1024)

    // load Q tile once (hi only, pre-scaled)
#pragma unroll
    for (int i = 0; i < 4; i++) {
        int lin = tid + i * 256;      // float4 index 0..1023
        int r   = lin >> 4;
        int c4  = (lin & 15) * 4;
        float4 v = *(const float4*)(qbase + (size_t)(q0 + r) * 64 + c4);
        float4 o;
        o.x = tf32_hi(v.x * invT);
        o.y = tf32_hi(v.y * invT);
        o.z = tf32_hi(v.z * invT);
        o.w = tf32_hi(v.w * invT);
        *(float4*)(Qh + r * 68 + c4) = o;
    }
    if (tid < 64) rs[tid] = 0.f;

    float o[4][4];
#pragma unroll
    for (int i = 0; i < 4; i++)
#pragma unroll
        for (int j = 0; j < 4; j++) o[i][j] = 0.f;

    for (int kt = 0; kt < 32; kt++) {
        const int k0 = kt * 64;
        // load K (hi) and V (transposed, hi/lo)
#pragma unroll
        for (int i = 0; i < 4; i++) {
            int lin = tid + i * 256;
            int r   = lin >> 4;
            int c4  = (lin & 15) * 4;
            float4 kv = *(const float4*)(kbase + (size_t)(k0 + r) * 64 + c4);
            float4 ko;
            ko.x = tf32_hi(kv.x); ko.y = tf32_hi(kv.y);
            ko.z = tf32_hi(kv.z); ko.w = tf32_hi(kv.w);
            *(float4*)(Kh + r * 68 + c4) = ko;

            float4 vv = *(const float4*)(vbase + (size_t)(k0 + r) * 64 + c4);
            float hx;
            hx = tf32_hi(vv.x); Vth[(c4 + 0) * 68 + r] = hx; Vtl[(c4 + 0) * 68 + r] = vv.x - hx;
            hx = tf32_hi(vv.y); Vth[(c4 + 1) * 68 + r] = hx; Vtl[(c4 + 1) * 68 + r] = vv.y - hx;
            hx = tf32_hi(vv.z); Vth[(c4 + 2) * 68 + r] = hx; Vtl[(c4 + 2) * 68 + r] = vv.z - hx;
            hx = tf32_hi(vv.w); Vth[(c4 + 3) * 68 + r] = hx; Vtl[(c4 + 3) * 68 + r] = vv.w - hx;
        }
        __syncthreads();

        // scores: S = Qs * K^T  (1x tf32)
        float s[4][4];
#pragma unroll
        for (int i = 0; i < 4; i++)
#pragma unroll
            for (int j = 0; j < 4; j++) s[i][j] = 0.f;

#pragma unroll
        for (int kg = 0; kg < 64; kg += 8) {
            int aoff = (wm * 16 + (lane >> 2)) * 68 + kg + (lane & 3);
            uint32_t a0 = __float_as_uint(Qh[aoff]);
            uint32_t a1 = __float_as_uint(Qh[aoff + 8 * 68]);
            uint32_t a2 = __float_as_uint(Qh[aoff + 4]);
            uint32_t a3 = __float_as_uint(Qh[aoff + 8 * 68 + 4]);
#pragma unroll
            for (int nt = 0; nt < 4; nt++) {
                int boff = (wn * 32 + nt * 8 + (lane >> 2)) * 68 + kg + (lane & 3);
                mma_tf32(s[nt], a0, a1, a2, a3,
                         __float_as_uint(Kh[boff]), __float_as_uint(Kh[boff + 4]));
            }
        }

        // exp, P hi/lo to smem, rowsum partials
        float rlo = 0.f, rhi = 0.f;
        const int rowb = wm * 16 + (lane >> 2);
#pragma unroll
        for (int nt = 0; nt < 4; nt++) {
            int colb = wn * 32 + nt * 8 + 2 * (lane & 3);
#pragma unroll
            for (int j = 0; j < 4; j++) {
                float p = __expf(s[nt][j]);
                int row = rowb + ((j >> 1) << 3);
                int col = colb + (j & 1);
                float ph = tf32_hi(p);
                Ph[row * 68 + col] = ph;
                Pl[row * 68 + col] = p - ph;
                if (j < 2) rlo += p; else rhi += p;
            }
        }
        rlo += __shfl_xor_sync(0xffffffffu, rlo, 1);
        rlo += __shfl_xor_sync(0xffffffffu, rlo, 2);
        rhi += __shfl_xor_sync(0xffffffffu, rhi, 1);
        rhi += __shfl_xor_sync(0xffffffffu, rhi, 2);
        if ((lane & 3) == 0) {
            atomicAdd(&rs[rowb], rlo);
            atomicAdd(&rs[rowb + 8], rhi);
        }
        __syncthreads();

        // write unnormalized P to gmem (coalesced float4)
        float* ab = attn_out + ((size_t)hb * S_ + q0) * S_ + k0;
#pragma unroll
        for (int i = 0; i < 4; i++) {
            int lin = tid + i * 256;
            int r   = lin >> 4;
            int c4  = (lin & 15) * 4;
            float4 pv;
            pv.x = Ph[r * 68 + c4 + 0] + Pl[r * 68 + c4 + 0];
            pv.y = Ph[r * 68 + c4 + 1] + Pl[r * 68 + c4 + 1];
            pv.z = Ph[r * 68 + c4 + 2] + Pl[r * 68 + c4 + 2];
            pv.w = Ph[r * 68 + c4 + 3] + Pl[r * 68 + c4 + 3];
            *(float4*)(ab + (size_t)r * S_ + c4) = pv;
        }

        // O += P @ V  (3xTF32)
#pragma unroll
        for (int kg = 0; kg < 64; kg += 8) {
            int aoff = (wm * 16 + (lane >> 2)) * 68 + kg + (lane & 3);
            uint32_t ah0 = __float_as_uint(Ph[aoff]);
            uint32_t ah1 = __float_as_uint(Ph[aoff + 8 * 68]);
            uint32_t ah2 = __float_as_uint(Ph[aoff + 4]);
            uint32_t ah3 = __float_as_uint(Ph[aoff + 8 * 68 + 4]);
            uint32_t al0 = __float_as_uint(Pl[aoff]);
            uint32_t al1 = __float_as_uint(Pl[aoff + 8 * 68]);
            uint32_t al2 = __float_as_uint(Pl[aoff + 4]);
            uint32_t al3 = __float_as_uint(Pl[aoff + 8 * 68 + 4]);
#pragma unroll
            for (int nt = 0; nt < 4; nt++) {
                int boff = (wn * 32 + nt * 8 + (lane >> 2)) * 68 + kg + (lane & 3);
                uint32_t bh0 = __float_as_uint(Vth[boff]);
                uint32_t bh1 = __float_as_uint(Vth[boff + 4]);
                uint32_t bl0 = __float_as_uint(Vtl[boff]);
                uint32_t bl1 = __float_as_uint(Vtl[boff + 4]);
                mma_tf32(o[nt], ah0, ah1, ah2, ah3, bh0, bh1);
                mma_tf32(o[nt], ah0, ah1, ah2, ah3, bl0, bl1);
                mma_tf32(o[nt], al0, al1, al2, al3, bh0, bh1);
            }
        }
        __syncthreads();
    }

    // invert rowsums once; publish for the normalize pass
    if (tid < 64) {
        float inv = 1.0f / rs[tid];
        g_rinv[(size_t)hb * S_ + q0 + tid] = inv;
        rs[tid] = inv;
    }
    __syncthreads();

    // write ctx = O * inv(rowsum), layout [b*S+s][h*64+d]
    const int rowb = wm * 16 + (lane >> 2);
#pragma unroll
    for (int nt = 0; nt < 4; nt++) {
        int colb = wn * 32 + nt * 8 + 2 * (lane & 3);
#pragma unroll
        for (int j = 0; j < 4; j++) {
            int row = rowb + ((j >> 1) << 3);
            int col = colb + (j & 1);
            float v = o[nt][j] * rs[row];
            g_ctx[((size_t)(b * S_ + q0 + row)) * D_ + h * DK_ + col] = v;
        }
    }
}

// ---------------------------------------------------------------------------
// Normalize attn in place: attn[hb][q][k] *= g_rinv[hb*S+q]
// ---------------------------------------------------------------------------
__global__ __launch_bounds__(256) void attn_norm(float* __restrict__ attn) {
    size_t i = (size_t)blockIdx.x * 256 + threadIdx.x;  // float4 index
    float inv = g_rinv[i >> 9];                          // 512 float4 per row
    float4* p = (float4*)attn;
    float4 v = p[i];
    v.x *= inv; v.y *= inv; v.z *= inv; v.w *= inv;
    p[i] = v;
}

// ---------------------------------------------------------------------------
// LayerNorm over rows of g_dense -> out
// ---------------------------------------------------------------------------
__global__ __launch_bounds__(256) void ln_kernel(const float* __restrict__ lg,
                                                 const float* __restrict__ lb,
                                                 float* __restrict__ out) {
    const int row = blockIdx.x;
    const int tid = threadIdx.x;
    const float* x = g_dense + (size_t)row * 1024;
    float4 xv = *(const float4*)(x + tid * 4);
    float s  = xv.x + xv.y + xv.z + xv.w;
    float ss = fmaf(xv.x, xv.x, fmaf(xv.y, xv.y, fmaf(xv.z, xv.z, xv.w * xv.w)));
#pragma unroll
    for (int off = 16; off > 0; off >>= 1) {
        s  += __shfl_xor_sync(0xffffffffu, s, off);
        ss += __shfl_xor_sync(0xffffffffu, ss, off);
    }
    __shared__ float sm1[8], sm2[8];
    if ((tid & 31) == 0) { sm1[tid >> 5] = s; sm2[tid >> 5] = ss; }
    __syncthreads();
    if (tid < 32) {
        float a  = (tid < 8) ? sm1[tid] : 0.f;
        float b2 = (tid < 8) ? sm2[tid] : 0.f;
#pragma unroll
        for (int off = 4; off > 0; off >>= 1) {
            a  += __shfl_xor_sync(0xffffffffu, a, off);
            b2 += __shfl_xor_sync(0xffffffffu, b2, off);
        }
        if (tid == 0) { sm1[0] = a; sm2[0] = b2; }
    }
    __syncthreads();
    float mean = sm1[0] * (1.0f / 1024.0f);
    float var  = sm2[0] * (1.0f / 1024.0f) - mean * mean;
    float rstd = rsqrtf(var + 1e-5f);
    float4 gv = *(const float4*)(lg + tid * 4);
    float4 bv = *(const float4*)(lb + tid * 4);
    float4 ov;
    ov.x = (xv.x - mean) * rstd * gv.x + bv.x;
    ov.y = (xv.y - mean) * rstd * gv.y + bv.y;
    ov.z = (xv.z - mean) * rstd * gv.z + bv.z;
    ov.w = (xv.w - mean) * rstd * gv.w + bv.w;
    *(float4*)(out + (size_t)row * 1024 + tid * 4) = ov;
}

// ---------------------------------------------------------------------------
// Launch
// ---------------------------------------------------------------------------
extern "C" void kernel_launch(void* const* d_in, const int* in_sizes, int n_in,
                              void* d_out, int out_size) {
    const float* k_in = (const float*)d_in[0];
    const float* q_in = (const float*)d_in[1];
    const float* wk   = (const float*)d_in[2];
    const float* bk   = (const float*)d_in[3];
    const float* wq   = (const float*)d_in[4];
    const float* bq   = (const float*)d_in[5];
    const float* wv   = (const float*)d_in[6];
    const float* bv   = (const float*)d_in[7];
    const float* wd   = (const float*)d_in[8];
    const float* bd   = (const float*)d_in[9];
    const float* lg   = (const float*)d_in[10];
    const float* lb   = (const float*)d_in[11];

    float* out  = (float*)d_out;
    float* attn = out + (size_t)B_ * S_ * D_;  // tuple order: (out, attn)

    const int attn_smem_bytes = ATTN_SMEM_FLOATS * 4;  // ~104.7 KB
    cudaFuncSetAttribute(attn_kernel, cudaFuncAttributeMaxDynamicSharedMemorySize,
                         attn_smem_bytes);

    dim3 pgrid(MTOT / 128, D_ / 128);  // (32, 8)
    proj_gemm<<<pgrid, 256>>>(q_in, wq, bq, 0);   // g_qx
    proj_gemm<<<pgrid, 256>>>(k_in, wk, bk, 1);   // g_kx
    proj_gemm<<<pgrid, 256>>>(k_in, wv, bv, 2);   // g_vx (v = k)

    attn_kernel<<<dim3(S_ / 64, HB_), 256, attn_smem_bytes>>>(attn);

    // 32*2048*2048/4 float4 = 33,554,432 -> 131072 blocks of 256
    attn_norm<<<131072, 256>>>(attn);

    proj_gemm<<<pgrid, 256>>>(nullptr, wd, bd, 3);  // dense + relu -> g_dense
    ln_kernel<<<MTOT, 256>>>(lg, lb, out);
}